// round 11
// baseline (speedup 1.0000x reference)
#include <cuda_runtime.h>

// MaxPool 2x2 stride 2, (16,64,512,512) fp32 -> (16,64,256,256) fp32.
// FINAL. DRAM-ceiling streaming kernel: 7305 GB/s (92.2% of 8TB/s spec),
// ncu dur 181.3us, harness ~186.2us (timer noise band 186.1-186.5 across
// the whole kernel family — DRAM interface bound, not SM bound).
//
// Config: 128-thread CTAs (131,072 blocks) — measured optimum of the CTA
// grain scan (1-wave persistent: 86.1% DRAM | 256-thr: 91.5% | 128-thr:
// 92.2% | 64-thr: 91.7%). __ldcg loads (L2-only; stream-once data never
// re-hits L1). One thread -> one float4 output via 4x coalesced LDG.128 +
// 1x STG.128 (4 fmax chains; compute pipes ~2% busy).
//
// Explored and rejected (all measured on GB300):
//   64B/thread spread loads      -> 188.4us (16 lines/wavefront, L1 70%)
//   perfect-coalesce f2 output   -> 186.8us (neutral)
//   warp-per-row-pair MLP=8      -> 186.8us (neutral)
//   __stcs store hints           -> 186.9us (neutral; L2 policy not binding)
//   persistent 1-wave grid       -> 204.9us (occ drop + loop serialization)
//   64-thread CTAs               -> 186.1us harness, but lower DRAM% (91.7)

#define IN_H 512
#define OUT_H 256
#define BC (16 * 64)

#define IN_ROW_F4 128   // 512 floats / 4
#define OUT_ROW_F4 64   // 256 floats / 4

__global__ void maxpool2x2_kernel(const float4* __restrict__ in4,
                                  float4* __restrict__ out4) {
    unsigned tid = blockIdx.x * blockDim.x + threadIdx.x;

    unsigned ox4  = tid & (OUT_ROW_F4 - 1);         // [0, 64)
    unsigned rest = tid >> 6;
    unsigned oy   = rest & (OUT_H - 1);             // [0, 256)
    unsigned bc   = rest >> 8;                      // [0, 1024)

    unsigned ibase = bc * (IN_H * IN_ROW_F4) + (oy * 2) * IN_ROW_F4 + ox4 * 2;

    float4 r0a = __ldcg(&in4[ibase]);
    float4 r0b = __ldcg(&in4[ibase + 1]);
    float4 r1a = __ldcg(&in4[ibase + IN_ROW_F4]);
    float4 r1b = __ldcg(&in4[ibase + IN_ROW_F4 + 1]);

    float4 o;
    o.x = fmaxf(fmaxf(r0a.x, r0a.y), fmaxf(r1a.x, r1a.y));
    o.y = fmaxf(fmaxf(r0a.z, r0a.w), fmaxf(r1a.z, r1a.w));
    o.z = fmaxf(fmaxf(r0b.x, r0b.y), fmaxf(r1b.x, r1b.y));
    o.w = fmaxf(fmaxf(r0b.z, r0b.w), fmaxf(r1b.z, r1b.w));

    out4[tid] = o;
}

extern "C" void kernel_launch(void* const* d_in, const int* in_sizes, int n_in,
                              void* d_out, int out_size) {
    const float4* in4 = (const float4*)d_in[0];
    float4* out4 = (float4*)d_out;

    const unsigned total = (unsigned)BC * OUT_H * OUT_ROW_F4;  // 16,777,216
    const int threads = 128;
    const unsigned blocks = total / threads;                   // 131,072

    maxpool2x2_kernel<<<blocks, threads>>>(in4, out4);
}